// round 14
// baseline (speedup 1.0000x reference)
#include <cuda_runtime.h>
#include <cstdint>

#define NCTA 128
#define NTHR 512
constexpr int B = 64, T = 1024, D = 256, H = 256;
constexpr int GROUPS = 8, P = 16, BG = 8, CPC = 16;

__device__ unsigned g_cnt[GROUPS][2][32];   // monotonic barrier counters
__device__ unsigned g_iarr[GROUPS][32];     // init barrier
__device__ unsigned g_igen[GROUPS][32];
__device__ unsigned g_abort = 0;
__device__ float g_hb[B * H];

__device__ __forceinline__ uint64_t packf2(float lo, float hi) {
    uint64_t d; asm("mov.b64 %0, {%1, %2};" : "=l"(d) : "f"(lo), "f"(hi)); return d;
}
__device__ __forceinline__ float2 unpackf2(uint64_t v) {
    float2 r; asm("mov.b64 {%0, %1}, %2;" : "=f"(r.x), "=f"(r.y) : "l"(v)); return r;
}
__device__ __forceinline__ uint64_t fma2(uint64_t a, uint64_t b, uint64_t c) {
    uint64_t d;
    asm("fma.rn.f32x2 %0, %1, %2, %3;" : "=l"(d) : "l"(a), "l"(b), "l"(c));
    return d;
}
__device__ __forceinline__ float sigmoid_fast(float x) {
    return __fdividef(1.0f, 1.0f + __expf(-x));
}
__device__ __forceinline__ float tanh_fast(float x) {
    float e = __expf(2.0f * x);
    return 1.0f - __fdividef(2.0f, e + 1.0f);
}
__device__ __forceinline__ void red_release(unsigned* ptr) {
    asm volatile("red.release.gpu.global.add.u32 [%0], 1;" :: "l"(ptr) : "memory");
}
__device__ __forceinline__ unsigned ld_acquire(const unsigned* ptr) {
    unsigned v;
    asm volatile("ld.acquire.gpu.global.u32 %0, [%1];" : "=r"(v) : "l"(ptr) : "memory");
    return v;
}

__global__ void __launch_bounds__(NTHR, 1) rgru_kernel(
    const float* __restrict__ x, const float* __restrict__ h0,
    const float* __restrict__ eps,
    const float* __restrict__ Wz, const float* __restrict__ bz,
    const float* __restrict__ Wr, const float* __restrict__ br,
    const float* __restrict__ Wtx, const float* __restrict__ btx,
    const float* __restrict__ Wth, const float* __restrict__ bth,
    const float* __restrict__ Wd, const float* __restrict__ bd,
    float* __restrict__ out)
{
    __shared__ unsigned sbs[2];
    __shared__ unsigned s_ig;

    const int tid = threadIdx.x, l = tid & 31, w = tid >> 5;
    const int g = blockIdx.x >> 4, p = blockIdx.x & 15;
    const int Jb = p * CPC, Bb = g * BG;
    const int j = Jb + w;

    // snapshot monotonic counters BEFORE any increments this launch
    if (tid < 2) sbs[tid] = *(volatile unsigned*)&g_cnt[g][tid][0];
    if (tid == 0) s_ig = *(volatile unsigned*)&g_igen[g][0];
    __syncthreads();
    const unsigned c0 = sbs[0], c1 = sbs[1];
    const unsigned ig = s_ig;

    // ---------------- packed weights into registers (once) ----------------
    uint64_t wz2[8], wr2[8], wu2[4], wv2[4], wm2[4], wlv2[4];
#pragma unroll
    for (int q = 0; q < 4; q++)
#pragma unroll
        for (int i = 0; i < 2; i++) {
            int k0 = 128 * q + 4 * l + 2 * i;
            wz2[2 * q + i] = packf2(Wz[k0 * H + j], Wz[(k0 + 1) * H + j]);
            wr2[2 * q + i] = packf2(Wr[k0 * H + j], Wr[(k0 + 1) * H + j]);
        }
#pragma unroll
    for (int q = 0; q < 2; q++)
#pragma unroll
        for (int i = 0; i < 2; i++) {
            int k0 = 128 * q + 4 * l + 2 * i;
            wu2[2 * q + i]  = packf2(Wtx[k0 * H + j], Wtx[(k0 + 1) * H + j]);
            wv2[2 * q + i]  = packf2(Wth[k0 * H + j], Wth[(k0 + 1) * H + j]);
            wm2[2 * q + i]  = packf2(Wd[k0 * 2 * H + j], Wd[(k0 + 1) * 2 * H + j]);
            wlv2[2 * q + i] = packf2(Wd[k0 * 2 * H + j + H], Wd[(k0 + 1) * 2 * H + j + H]);
        }
    const float bzj = bz[j], brj = br[j], btxj = btx[j], bthj = bth[j];
    const float bmj = bd[j], blj = bd[j + H];

    // ---- one-time fenced init barrier: closes the snapshot race ----
    __syncthreads();
    if (tid == 0) {
        __threadfence();
        unsigned a = atomicAdd(&g_iarr[g][0], 1u);
        if (((a + 1u) % (unsigned)P) == 0u) {
            __threadfence();
            atomicExch(&g_igen[g][0], ig + 1u);
        }
        volatile unsigned* ip = &g_igen[g][0];
        long long t0 = clock64();
        while ((int)(*ip - (ig + 1u)) < 0) {
            if (clock64() - t0 > 2000000000LL) { atomicExch(&g_abort, 1u); break; }
        }
        __threadfence();
    }
    __syncthreads();

    // wait: acquire-poll monotonic counter (bounded so GPU can never hang)
    auto waitc = [&](int id, unsigned base, unsigned steps) {
        const unsigned tgt = base + steps * 256u;
        const unsigned* ptr = &g_cnt[g][id][0];
        unsigned v = ld_acquire(ptr);
        if ((int)(v - tgt) < 0) {
            long long t0 = clock64();
            do {
                if (*(volatile unsigned*)&g_abort) return;
                if (clock64() - t0 > 2000000000LL) { atomicExch(&g_abort, 1u); return; }
                v = ld_acquire(ptr);
            } while ((int)(v - tgt) < 0);
        }
    };

    // phase 1: all 8 batches -> g_hb, then release barrier 0
    auto phase1 = [&](int t) {
        float fin = 0.f;
        const int pb = Bb + (l & 7);
        const float* hrow_t = (t == 0) ? (h0 + pb * H)
                                       : (out + ((size_t)pb * T + (t - 1)) * H);
        float hpsel = __ldcg(hrow_t + j);
#pragma unroll
        for (int bb = 0; bb < 8; bb++) {
            const int b = Bb + bb;
            const float* xrow = x + ((size_t)b * T + t) * D;
            const float* hrow = (t == 0) ? (h0 + b * H)
                                         : (out + ((size_t)b * T + (t - 1)) * H);
            float4 xv0 = __ldg((const float4*)xrow + l);
            float4 xv1 = __ldg((const float4*)xrow + 32 + l);
            float4 hv0 = __ldcg((const float4*)hrow + l);
            float4 hv1 = __ldcg((const float4*)hrow + 32 + l);
            uint64_t a2[8] = { packf2(xv0.x, xv0.y), packf2(xv0.z, xv0.w),
                               packf2(xv1.x, xv1.y), packf2(xv1.z, xv1.w),
                               packf2(hv0.x, hv0.y), packf2(hv0.z, hv0.w),
                               packf2(hv1.x, hv1.y), packf2(hv1.z, hv1.w) };
            uint64_t sz2 = 0, sr2 = 0, su2 = 0, sv2 = 0;
#pragma unroll
            for (int i = 0; i < 8; i++) {
                sz2 = fma2(wz2[i], a2[i], sz2);
                sr2 = fma2(wr2[i], a2[i], sr2);
            }
#pragma unroll
            for (int i = 0; i < 4; i++) {
                su2 = fma2(wu2[i], a2[i], su2);
                sv2 = fma2(wv2[i], a2[4 + i], sv2);
            }
            float2 f;
            f = unpackf2(sz2); float sz = f.x + f.y;
            f = unpackf2(sr2); float sr = f.x + f.y;
            f = unpackf2(su2); float su = f.x + f.y;
            f = unpackf2(sv2); float sv = f.x + f.y;
            // 6-shfl 4-value reduction: z->lanes0-7, r->8-15, u->16-23, v->24-31
            const bool hi16 = (l & 16) != 0;
            float sA = hi16 ? sz : su;
            float rA = __shfl_xor_sync(0xffffffffu, sA, 16);
            float zu = hi16 ? (su + rA) : (sz + rA);
            float sB = hi16 ? sr : sv;
            float rB = __shfl_xor_sync(0xffffffffu, sB, 16);
            float rv = hi16 ? (sv + rB) : (sr + rB);
            const bool hi8 = (l & 8) != 0;
            float sC = hi8 ? zu : rv;
            float rC = __shfl_xor_sync(0xffffffffu, sC, 8);
            float myv = hi8 ? (rv + rC) : (zu + rC);
            myv += __shfl_xor_sync(0xffffffffu, myv, 4);
            myv += __shfl_xor_sync(0xffffffffu, myv, 2);
            myv += __shfl_xor_sync(0xffffffffu, myv, 1);
            fin = ((l & 7) == bb) ? myv : fin;
        }
        const int tb = l & 7;
        float zs = __shfl_sync(0xffffffffu, fin, tb);
        float rs = __shfl_sync(0xffffffffu, fin, tb + 8);
        float us = __shfl_sync(0xffffffffu, fin, tb + 16);
        float vs = __shfl_sync(0xffffffffu, fin, tb + 24);
        float z  = sigmoid_fast(zs + bzj);
        float r  = sigmoid_fast(rs + brj);
        float th = tanh_fast(us + btxj + r * (vs + bthj));
        float hbv = fmaf(z, hpsel - th, th);         // z*hp + (1-z)*th
        if (l < 8) __stcg(&g_hb[(Bb + l) * H + j], hbv);
        if (l == 0) red_release(&g_cnt[g][0][0]);
    };

    // phase 2: all 8 batches -> sample(out), then release barrier 1
    auto phase2 = [&](int t) {
        float fin = 0.f;
#pragma unroll
        for (int bb = 0; bb < 8; bb++) {
            const float* hbrow = g_hb + (Bb + bb) * H;
            float4 q0 = __ldcg((const float4*)hbrow + l);
            float4 q1 = __ldcg((const float4*)hbrow + 32 + l);
            uint64_t h2[4] = { packf2(q0.x, q0.y), packf2(q0.z, q0.w),
                               packf2(q1.x, q1.y), packf2(q1.z, q1.w) };
            uint64_t sm2 = 0, sl2 = 0;
#pragma unroll
            for (int i = 0; i < 4; i++) {
                sm2 = fma2(wm2[i], h2[i], sm2);
                sl2 = fma2(wlv2[i], h2[i], sl2);
            }
            float2 f;
            f = unpackf2(sm2); float sm = f.x + f.y;
            f = unpackf2(sl2); float sl = f.x + f.y;
            // 5-shfl 2-value reduction: m->lanes0-15, lv->16-31
            const bool hi16 = (l & 16) != 0;
            float sA = hi16 ? sm : sl;
            float rA = __shfl_xor_sync(0xffffffffu, sA, 16);
            float mv = hi16 ? (sl + rA) : (sm + rA);
            mv += __shfl_xor_sync(0xffffffffu, mv, 8);
            mv += __shfl_xor_sync(0xffffffffu, mv, 4);
            mv += __shfl_xor_sync(0xffffffffu, mv, 2);
            mv += __shfl_xor_sync(0xffffffffu, mv, 1);
            fin = ((l & 15) == bb) ? mv : fin;
        }
        const int tb = l & 7;
        float ms = __shfl_sync(0xffffffffu, fin, tb);
        float ls = __shfl_sync(0xffffffffu, fin, tb + 16);
        float mean = fminf(fmaxf(ms + bmj, -1000.0f), 1000.0f);
        float lv   = fminf(fmaxf(ls + blj, -30.0f), 30.0f);
        float ep   = __ldg(eps + ((size_t)(Bb + tb) * T + t) * H + j);
        float s    = fmaf(__expf(0.5f * lv), ep, mean);
        if (l < 8) {
            const int b = Bb + l;
            __stcg(&out[((size_t)b * T + t) * H + j], s);
            if (t == T - 1) out[(size_t)B * T * H + b * H + j] = s;
        }
        if (l == 0) red_release(&g_cnt[g][1][0]);
    };

    // ---------------- main loop: 2 barriers per step ----------------
    for (int t = 0; t < T; t++) {
        const unsigned st = (unsigned)t;

        if (t > 0) waitc(1, c1, st);   // sample(t-1) complete group-wide
        phase1(t);

        waitc(0, c0, st + 1u);         // h_base complete group-wide
        phase2(t);
    }
}

extern "C" void kernel_launch(void* const* d_in, const int* in_sizes, int n_in,
                              void* d_out, int out_size) {
    const float* x   = (const float*)d_in[0];
    const float* h0  = (const float*)d_in[1];
    const float* eps = (const float*)d_in[2];
    const float* Wz  = (const float*)d_in[3];
    const float* bz  = (const float*)d_in[4];
    const float* Wr  = (const float*)d_in[5];
    const float* br  = (const float*)d_in[6];
    const float* Wtx = (const float*)d_in[7];
    const float* btx = (const float*)d_in[8];
    const float* Wth = (const float*)d_in[9];
    const float* bth = (const float*)d_in[10];
    const float* Wd  = (const float*)d_in[11];
    const float* bd  = (const float*)d_in[12];
    float* out = (float*)d_out;

    rgru_kernel<<<NCTA, NTHR>>>(x, h0, eps, Wz, bz, Wr, br,
                                Wtx, btx, Wth, bth, Wd, bd, out);
}

// round 15
// speedup vs baseline: 1.3876x; 1.3876x over previous
#include <cuda_runtime.h>
#include <cstdint>

#define NCTA 128
#define NTHR 512
constexpr int B = 64, T = 1024, D = 256, H = 256;
constexpr int GROUPS = 8, P = 16, BG = 8, CPC = 16;

__device__ unsigned g_cnt[GROUPS][2][32];   // monotonic barrier counters
__device__ unsigned g_iarr[GROUPS][32];     // init barrier
__device__ unsigned g_igen[GROUPS][32];
__device__ unsigned g_abort = 0;
__device__ float g_hb[B * H];

__device__ __forceinline__ uint64_t packf2(float lo, float hi) {
    uint64_t d; asm("mov.b64 %0, {%1, %2};" : "=l"(d) : "f"(lo), "f"(hi)); return d;
}
__device__ __forceinline__ float2 unpackf2(uint64_t v) {
    float2 r; asm("mov.b64 {%0, %1}, %2;" : "=f"(r.x), "=f"(r.y) : "l"(v)); return r;
}
__device__ __forceinline__ uint64_t fma2(uint64_t a, uint64_t b, uint64_t c) {
    uint64_t d;
    asm("fma.rn.f32x2 %0, %1, %2, %3;" : "=l"(d) : "l"(a), "l"(b), "l"(c));
    return d;
}
__device__ __forceinline__ float sigmoid_fast(float x) {
    return __fdividef(1.0f, 1.0f + __expf(-x));
}
__device__ __forceinline__ float tanh_fast(float x) {
    float e = __expf(2.0f * x);
    return 1.0f - __fdividef(2.0f, e + 1.0f);
}
__device__ __forceinline__ void red_release(unsigned* ptr) {
    asm volatile("red.release.gpu.global.add.u32 [%0], 1;" :: "l"(ptr) : "memory");
}
__device__ __forceinline__ unsigned ld_acquire(const unsigned* ptr) {
    unsigned v;
    asm volatile("ld.acquire.gpu.global.u32 %0, [%1];" : "=r"(v) : "l"(ptr) : "memory");
    return v;
}

__global__ void __launch_bounds__(NTHR, 1) rgru_kernel(
    const float* __restrict__ x, const float* __restrict__ h0,
    const float* __restrict__ eps,
    const float* __restrict__ Wz, const float* __restrict__ bz,
    const float* __restrict__ Wr, const float* __restrict__ br,
    const float* __restrict__ Wtx, const float* __restrict__ btx,
    const float* __restrict__ Wth, const float* __restrict__ bth,
    const float* __restrict__ Wd, const float* __restrict__ bd,
    float* __restrict__ out)
{
    __shared__ __align__(16) float x_s[BG][256];    // x(t)
    __shared__ __align__(16) float hx_s[BG][256];   // h(t-1)
    __shared__ __align__(16) float hb_s[BG][256];   // h_base(t)
    __shared__ unsigned sbs[2];
    __shared__ unsigned s_ig;

    const int tid = threadIdx.x, l = tid & 31, w = tid >> 5;
    const int g = blockIdx.x >> 4, p = blockIdx.x & 15;
    const int Jb = p * CPC, Bb = g * BG;
    const int j = Jb + w;
    const int sb_ = tid >> 6, sq = tid & 63;   // staging coords: row 0..7, float4 0..63

    // snapshot monotonic counters BEFORE any increments this launch
    if (tid < 2) sbs[tid] = *(volatile unsigned*)&g_cnt[g][tid][0];
    if (tid == 0) s_ig = *(volatile unsigned*)&g_igen[g][0];
    __syncthreads();
    const unsigned c0 = sbs[0], c1 = sbs[1];
    const unsigned ig = s_ig;

    // ---------------- packed weights into registers (once) ----------------
    uint64_t wz2[8], wr2[8], wu2[4], wv2[4], wm2[4], wlv2[4];
#pragma unroll
    for (int q = 0; q < 4; q++)
#pragma unroll
        for (int i = 0; i < 2; i++) {
            int k0 = 128 * q + 4 * l + 2 * i;
            wz2[2 * q + i] = packf2(Wz[k0 * H + j], Wz[(k0 + 1) * H + j]);
            wr2[2 * q + i] = packf2(Wr[k0 * H + j], Wr[(k0 + 1) * H + j]);
        }
#pragma unroll
    for (int q = 0; q < 2; q++)
#pragma unroll
        for (int i = 0; i < 2; i++) {
            int k0 = 128 * q + 4 * l + 2 * i;
            wu2[2 * q + i]  = packf2(Wtx[k0 * H + j], Wtx[(k0 + 1) * H + j]);
            wv2[2 * q + i]  = packf2(Wth[k0 * H + j], Wth[(k0 + 1) * H + j]);
            wm2[2 * q + i]  = packf2(Wd[k0 * 2 * H + j], Wd[(k0 + 1) * 2 * H + j]);
            wlv2[2 * q + i] = packf2(Wd[k0 * 2 * H + j + H], Wd[(k0 + 1) * 2 * H + j + H]);
        }
    const float bzj = bz[j], brj = br[j], btxj = btx[j], bthj = bth[j];
    const float bmj = bd[j], blj = bd[j + H];

    // ---- one-time fenced init barrier: closes the snapshot race ----
    __syncthreads();
    if (tid == 0) {
        __threadfence();
        unsigned a = atomicAdd(&g_iarr[g][0], 1u);
        if (((a + 1u) % (unsigned)P) == 0u) {
            __threadfence();
            atomicExch(&g_igen[g][0], ig + 1u);
        }
        volatile unsigned* ip = &g_igen[g][0];
        long long t0 = clock64();
        while ((int)(*ip - (ig + 1u)) < 0) {
            if (clock64() - t0 > 2000000000LL) { atomicExch(&g_abort, 1u); break; }
        }
        __threadfence();
    }
    __syncthreads();

    // wait: acquire-poll monotonic counter (bounded so GPU can never hang)
    auto waitc = [&](int id, unsigned base, unsigned steps) {
        const unsigned tgt = base + steps * 256u;
        const unsigned* ptr = &g_cnt[g][id][0];
        unsigned v = ld_acquire(ptr);
        if ((int)(v - tgt) < 0) {
            long long t0 = clock64();
            do {
                if (*(volatile unsigned*)&g_abort) return;
                if (clock64() - t0 > 2000000000LL) { atomicExch(&g_abort, 1u); return; }
                v = ld_acquire(ptr);
            } while ((int)(v - tgt) < 0);
        }
    };

    // cooperative staging: one float4 per thread per buffer (512 in flight)
    auto stage_xh = [&](int t) {
        float4 xv = __ldg((const float4*)(x + ((size_t)(Bb + sb_) * T + t) * D) + sq);
        float4 hv;
        if (t == 0) hv = *((const float4*)(h0 + (Bb + sb_) * H) + sq);
        else        hv = __ldcg((const float4*)(out + ((size_t)(Bb + sb_) * T + (t - 1)) * H) + sq);
        ((float4*)x_s[sb_])[sq]  = xv;
        ((float4*)hx_s[sb_])[sq] = hv;
    };
    auto stage_hb = [&]() {
        ((float4*)hb_s[sb_])[sq] =
            __ldcg((const float4*)(g_hb + (Bb + sb_) * H) + sq);
    };

    // phase 1: all 8 batches -> g_hb, then release barrier 0
    auto phase1 = [&]() {
        float fin = 0.f;
        float hpsel = hx_s[l & 7][j];
#pragma unroll
        for (int bb = 0; bb < 8; bb++) {
            const float4* xrow4 = (const float4*)x_s[bb];
            const float4* hrow4 = (const float4*)hx_s[bb];
            float4 xv0 = xrow4[l], xv1 = xrow4[32 + l];
            float4 hv0 = hrow4[l], hv1 = hrow4[32 + l];
            uint64_t a2[8] = { packf2(xv0.x, xv0.y), packf2(xv0.z, xv0.w),
                               packf2(xv1.x, xv1.y), packf2(xv1.z, xv1.w),
                               packf2(hv0.x, hv0.y), packf2(hv0.z, hv0.w),
                               packf2(hv1.x, hv1.y), packf2(hv1.z, hv1.w) };
            uint64_t sz2 = 0, sr2 = 0, su2 = 0, sv2 = 0;
#pragma unroll
            for (int i = 0; i < 8; i++) {
                sz2 = fma2(wz2[i], a2[i], sz2);
                sr2 = fma2(wr2[i], a2[i], sr2);
            }
#pragma unroll
            for (int i = 0; i < 4; i++) {
                su2 = fma2(wu2[i], a2[i], su2);
                sv2 = fma2(wv2[i], a2[4 + i], sv2);
            }
            float2 f;
            f = unpackf2(sz2); float sz = f.x + f.y;
            f = unpackf2(sr2); float sr = f.x + f.y;
            f = unpackf2(su2); float su = f.x + f.y;
            f = unpackf2(sv2); float sv = f.x + f.y;
            // 6-shfl 4-value reduction: z->lanes0-7, r->8-15, u->16-23, v->24-31
            const bool hi16 = (l & 16) != 0;
            float sA = hi16 ? sz : su;
            float rA = __shfl_xor_sync(0xffffffffu, sA, 16);
            float zu = hi16 ? (su + rA) : (sz + rA);
            float sB = hi16 ? sr : sv;
            float rB = __shfl_xor_sync(0xffffffffu, sB, 16);
            float rv = hi16 ? (sv + rB) : (sr + rB);
            const bool hi8 = (l & 8) != 0;
            float sC = hi8 ? zu : rv;
            float rC = __shfl_xor_sync(0xffffffffu, sC, 8);
            float myv = hi8 ? (rv + rC) : (zu + rC);
            myv += __shfl_xor_sync(0xffffffffu, myv, 4);
            myv += __shfl_xor_sync(0xffffffffu, myv, 2);
            myv += __shfl_xor_sync(0xffffffffu, myv, 1);
            fin = ((l & 7) == bb) ? myv : fin;
        }
        const int tb = l & 7;
        float zs = __shfl_sync(0xffffffffu, fin, tb);
        float rs = __shfl_sync(0xffffffffu, fin, tb + 8);
        float us = __shfl_sync(0xffffffffu, fin, tb + 16);
        float vs = __shfl_sync(0xffffffffu, fin, tb + 24);
        float z  = sigmoid_fast(zs + bzj);
        float r  = sigmoid_fast(rs + brj);
        float th = tanh_fast(us + btxj + r * (vs + bthj));
        float hbv = fmaf(z, hpsel - th, th);         // z*hp + (1-z)*th
        if (l < 8) __stcg(&g_hb[(Bb + l) * H + j], hbv);
        if (l == 0) red_release(&g_cnt[g][0][0]);
    };

    // phase 2: all 8 batches -> sample(out), then release barrier 1
    auto phase2 = [&](int t) {
        float fin = 0.f;
#pragma unroll
        for (int bb = 0; bb < 8; bb++) {
            const float4* hbrow4 = (const float4*)hb_s[bb];
            float4 q0 = hbrow4[l], q1 = hbrow4[32 + l];
            uint64_t h2[4] = { packf2(q0.x, q0.y), packf2(q0.z, q0.w),
                               packf2(q1.x, q1.y), packf2(q1.z, q1.w) };
            uint64_t sm2 = 0, sl2 = 0;
#pragma unroll
            for (int i = 0; i < 4; i++) {
                sm2 = fma2(wm2[i], h2[i], sm2);
                sl2 = fma2(wlv2[i], h2[i], sl2);
            }
            float2 f;
            f = unpackf2(sm2); float sm = f.x + f.y;
            f = unpackf2(sl2); float sl = f.x + f.y;
            // 5-shfl 2-value reduction: m->lanes0-15, lv->16-31
            const bool hi16 = (l & 16) != 0;
            float sA = hi16 ? sm : sl;
            float rA = __shfl_xor_sync(0xffffffffu, sA, 16);
            float mv = hi16 ? (sl + rA) : (sm + rA);
            mv += __shfl_xor_sync(0xffffffffu, mv, 8);
            mv += __shfl_xor_sync(0xffffffffu, mv, 4);
            mv += __shfl_xor_sync(0xffffffffu, mv, 2);
            mv += __shfl_xor_sync(0xffffffffu, mv, 1);
            fin = ((l & 15) == bb) ? mv : fin;
        }
        const int tb = l & 7;
        float ms = __shfl_sync(0xffffffffu, fin, tb);
        float ls = __shfl_sync(0xffffffffu, fin, tb + 16);
        float mean = fminf(fmaxf(ms + bmj, -1000.0f), 1000.0f);
        float lv   = fminf(fmaxf(ls + blj, -30.0f), 30.0f);
        float ep   = __ldg(eps + ((size_t)(Bb + tb) * T + t) * H + j);
        float s    = fmaf(__expf(0.5f * lv), ep, mean);
        if (l < 8) {
            const int b = Bb + l;
            __stcg(&out[((size_t)b * T + t) * H + j], s);
            if (t == T - 1) out[(size_t)B * T * H + b * H + j] = s;
        }
        if (l == 0) red_release(&g_cnt[g][1][0]);
    };

    // ---------------- main loop: 2 barriers per step ----------------
    for (int t = 0; t < T; t++) {
        const unsigned st = (unsigned)t;

        if (t > 0) waitc(1, c1, st);   // sample(t-1) complete group-wide
        stage_xh(t);                   // burst-load x(t) + h(t-1) into smem
        __syncthreads();
        phase1();

        waitc(0, c0, st + 1u);         // h_base complete group-wide
        stage_hb();                    // burst-load h_base into smem
        __syncthreads();
        phase2(t);
    }
}

extern "C" void kernel_launch(void* const* d_in, const int* in_sizes, int n_in,
                              void* d_out, int out_size) {
    const float* x   = (const float*)d_in[0];
    const float* h0  = (const float*)d_in[1];
    const float* eps = (const float*)d_in[2];
    const float* Wz  = (const float*)d_in[3];
    const float* bz  = (const float*)d_in[4];
    const float* Wr  = (const float*)d_in[5];
    const float* br  = (const float*)d_in[6];
    const float* Wtx = (const float*)d_in[7];
    const float* btx = (const float*)d_in[8];
    const float* Wth = (const float*)d_in[9];
    const float* bth = (const float*)d_in[10];
    const float* Wd  = (const float*)d_in[11];
    const float* bd  = (const float*)d_in[12];
    float* out = (float*)d_out;

    rgru_kernel<<<NCTA, NTHR>>>(x, h0, eps, Wz, bz, Wr, br,
                                Wtx, btx, Wth, bth, Wd, bd, out);
}

// round 17
// speedup vs baseline: 1.3967x; 1.0066x over previous
#include <cuda_runtime.h>
#include <cstdint>

#define NCTA 128
#define NTHR 512
constexpr int B = 64, T = 1024, D = 256, H = 256;
constexpr int GROUPS = 8, P = 16, BG = 8, CPC = 16;

__device__ unsigned g_cnt[GROUPS][2][16][32];  // spread counters: 1 line per consumer CTA
__device__ unsigned g_iarr[GROUPS][32];        // init barrier
__device__ unsigned g_igen[GROUPS][32];
__device__ unsigned g_abort = 0;
__device__ float g_hb[B * H];

__device__ __forceinline__ uint64_t packf2(float lo, float hi) {
    uint64_t d; asm("mov.b64 %0, {%1, %2};" : "=l"(d) : "f"(lo), "f"(hi)); return d;
}
__device__ __forceinline__ float2 unpackf2(uint64_t v) {
    float2 r; asm("mov.b64 {%0, %1}, %2;" : "=f"(r.x), "=f"(r.y) : "l"(v)); return r;
}
__device__ __forceinline__ uint64_t fma2(uint64_t a, uint64_t b, uint64_t c) {
    uint64_t d;
    asm("fma.rn.f32x2 %0, %1, %2, %3;" : "=l"(d) : "l"(a), "l"(b), "l"(c));
    return d;
}
__device__ __forceinline__ float sigmoid_fast(float x) {
    return __fdividef(1.0f, 1.0f + __expf(-x));
}
__device__ __forceinline__ float tanh_fast(float x) {
    float e = __expf(2.0f * x);
    return 1.0f - __fdividef(2.0f, e + 1.0f);
}
__device__ __forceinline__ void red_release(unsigned* ptr) {
    asm volatile("red.release.gpu.global.add.u32 [%0], 1;" :: "l"(ptr) : "memory");
}
__device__ __forceinline__ unsigned ld_acquire(const unsigned* ptr) {
    unsigned v;
    asm volatile("ld.acquire.gpu.global.u32 %0, [%1];" : "=r"(v) : "l"(ptr) : "memory");
    return v;
}

__global__ void __launch_bounds__(NTHR, 1) rgru_kernel(
    const float* __restrict__ x, const float* __restrict__ h0,
    const float* __restrict__ eps,
    const float* __restrict__ Wz, const float* __restrict__ bz,
    const float* __restrict__ Wr, const float* __restrict__ br,
    const float* __restrict__ Wtx, const float* __restrict__ btx,
    const float* __restrict__ Wth, const float* __restrict__ bth,
    const float* __restrict__ Wd, const float* __restrict__ bd,
    float* __restrict__ out)
{
    __shared__ __align__(16) float x_s[BG][256];    // x(t)
    __shared__ __align__(16) float hx_s[BG][256];   // h(t-1)
    __shared__ __align__(16) float hb_s[BG][256];   // h_base(t)
    __shared__ unsigned sbs[2];
    __shared__ unsigned s_ig;

    const int tid = threadIdx.x, l = tid & 31, w = tid >> 5;
    const int g = blockIdx.x >> 4, p = blockIdx.x & 15;
    const int Jb = p * CPC, Bb = g * BG;
    const int j = Jb + w;
    const int sb_ = tid >> 6, sq = tid & 63;   // staging coords

    // snapshot THIS CTA's counter copies before any increments this launch
    if (tid < 2) sbs[tid] = *(volatile unsigned*)&g_cnt[g][tid][p][0];
    if (tid == 0) s_ig = *(volatile unsigned*)&g_igen[g][0];
    __syncthreads();
    const unsigned c0 = sbs[0], c1 = sbs[1];
    const unsigned ig = s_ig;

    // ---------------- packed weights into registers (once) ----------------
    uint64_t wz2[8], wr2[8], wu2[4], wv2[4], wm2[4], wlv2[4];
#pragma unroll
    for (int q = 0; q < 4; q++)
#pragma unroll
        for (int i = 0; i < 2; i++) {
            int k0 = 128 * q + 4 * l + 2 * i;
            wz2[2 * q + i] = packf2(Wz[k0 * H + j], Wz[(k0 + 1) * H + j]);
            wr2[2 * q + i] = packf2(Wr[k0 * H + j], Wr[(k0 + 1) * H + j]);
        }
#pragma unroll
    for (int q = 0; q < 2; q++)
#pragma unroll
        for (int i = 0; i < 2; i++) {
            int k0 = 128 * q + 4 * l + 2 * i;
            wu2[2 * q + i]  = packf2(Wtx[k0 * H + j], Wtx[(k0 + 1) * H + j]);
            wv2[2 * q + i]  = packf2(Wth[k0 * H + j], Wth[(k0 + 1) * H + j]);
            wm2[2 * q + i]  = packf2(Wd[k0 * 2 * H + j], Wd[(k0 + 1) * 2 * H + j]);
            wlv2[2 * q + i] = packf2(Wd[k0 * 2 * H + j + H], Wd[(k0 + 1) * 2 * H + j + H]);
        }
    const float bzj = bz[j], brj = br[j], btxj = btx[j], bthj = bth[j];
    const float bmj = bd[j], blj = bd[j + H];

    // ---- one-time fenced init barrier: closes the snapshot race ----
    __syncthreads();
    if (tid == 0) {
        __threadfence();
        unsigned a = atomicAdd(&g_iarr[g][0], 1u);
        if (((a + 1u) % (unsigned)P) == 0u) {
            __threadfence();
            atomicExch(&g_igen[g][0], ig + 1u);
        }
        volatile unsigned* ip = &g_igen[g][0];
        long long t0 = clock64();
        while ((int)(*ip - (ig + 1u)) < 0) {
            if (clock64() - t0 > 2000000000LL) { atomicExch(&g_abort, 1u); break; }
        }
        __threadfence();
    }
    __syncthreads();

    // wait: acquire-poll THIS CTA's counter copy (bounded; GPU can never hang)
    auto waitc = [&](int id, unsigned base, unsigned steps) {
        const unsigned tgt = base + steps * 256u;
        const unsigned* ptr = &g_cnt[g][id][p][0];
        unsigned v = ld_acquire(ptr);
        if ((int)(v - tgt) < 0) {
            long long t0 = clock64();
            do {
                if (*(volatile unsigned*)&g_abort) return;
                if (clock64() - t0 > 2000000000LL) { atomicExch(&g_abort, 1u); return; }
                v = ld_acquire(ptr);
            } while ((int)(v - tgt) < 0);
        }
    };
    // release: lanes 0-15 each increment one consumer CTA's copy
    auto release = [&](int id) {
        if (l < 16) red_release(&g_cnt[g][id][l][0]);
    };

    // phase 1: all 8 batches -> g_hb, then release barrier 0
    auto phase1 = [&]() {
        float fin = 0.f;
        float hpsel = hx_s[l & 7][j];
#pragma unroll
        for (int bb = 0; bb < 8; bb++) {
            const float4* xrow4 = (const float4*)x_s[bb];
            const float4* hrow4 = (const float4*)hx_s[bb];
            float4 xv0 = xrow4[l], xv1 = xrow4[32 + l];
            float4 hv0 = hrow4[l], hv1 = hrow4[32 + l];
            uint64_t a2[8] = { packf2(xv0.x, xv0.y), packf2(xv0.z, xv0.w),
                               packf2(xv1.x, xv1.y), packf2(xv1.z, xv1.w),
                               packf2(hv0.x, hv0.y), packf2(hv0.z, hv0.w),
                               packf2(hv1.x, hv1.y), packf2(hv1.z, hv1.w) };
            uint64_t sz2 = 0, sr2 = 0, su2 = 0, sv2 = 0;
#pragma unroll
            for (int i = 0; i < 8; i++) {
                sz2 = fma2(wz2[i], a2[i], sz2);
                sr2 = fma2(wr2[i], a2[i], sr2);
            }
#pragma unroll
            for (int i = 0; i < 4; i++) {
                su2 = fma2(wu2[i], a2[i], su2);
                sv2 = fma2(wv2[i], a2[4 + i], sv2);
            }
            float2 f;
            f = unpackf2(sz2); float sz = f.x + f.y;
            f = unpackf2(sr2); float sr = f.x + f.y;
            f = unpackf2(su2); float su = f.x + f.y;
            f = unpackf2(sv2); float sv = f.x + f.y;
            // 6-shfl 4-value reduction: z->lanes0-7, r->8-15, u->16-23, v->24-31
            const bool hi16 = (l & 16) != 0;
            float sA = hi16 ? sz : su;
            float rA = __shfl_xor_sync(0xffffffffu, sA, 16);
            float zu = hi16 ? (su + rA) : (sz + rA);
            float sB = hi16 ? sr : sv;
            float rB = __shfl_xor_sync(0xffffffffu, sB, 16);
            float rv = hi16 ? (sv + rB) : (sr + rB);
            const bool hi8 = (l & 8) != 0;
            float sC = hi8 ? zu : rv;
            float rC = __shfl_xor_sync(0xffffffffu, sC, 8);
            float myv = hi8 ? (rv + rC) : (zu + rC);
            myv += __shfl_xor_sync(0xffffffffu, myv, 4);
            myv += __shfl_xor_sync(0xffffffffu, myv, 2);
            myv += __shfl_xor_sync(0xffffffffu, myv, 1);
            fin = ((l & 7) == bb) ? myv : fin;
        }
        const int tb = l & 7;
        float zs = __shfl_sync(0xffffffffu, fin, tb);
        float rs = __shfl_sync(0xffffffffu, fin, tb + 8);
        float us = __shfl_sync(0xffffffffu, fin, tb + 16);
        float vs = __shfl_sync(0xffffffffu, fin, tb + 24);
        float z  = sigmoid_fast(zs + bzj);
        float r  = sigmoid_fast(rs + brj);
        float th = tanh_fast(us + btxj + r * (vs + bthj));
        float hbv = fmaf(z, hpsel - th, th);         // z*hp + (1-z)*th
        if (l < 8) __stcg(&g_hb[(Bb + l) * H + j], hbv);
        release(0);
    };

    // phase 2: all 8 batches -> sample(out), then release barrier 1
    auto phase2 = [&](int t, float ep) {
        float fin = 0.f;
#pragma unroll
        for (int bb = 0; bb < 8; bb++) {
            const float4* hbrow4 = (const float4*)hb_s[bb];
            float4 q0 = hbrow4[l], q1 = hbrow4[32 + l];
            uint64_t h2[4] = { packf2(q0.x, q0.y), packf2(q0.z, q0.w),
                               packf2(q1.x, q1.y), packf2(q1.z, q1.w) };
            uint64_t sm2 = 0, sl2 = 0;
#pragma unroll
            for (int i = 0; i < 4; i++) {
                sm2 = fma2(wm2[i], h2[i], sm2);
                sl2 = fma2(wlv2[i], h2[i], sl2);
            }
            float2 f;
            f = unpackf2(sm2); float sm = f.x + f.y;
            f = unpackf2(sl2); float sl = f.x + f.y;
            // 5-shfl 2-value reduction: m->lanes0-15, lv->16-31
            const bool hi16 = (l & 16) != 0;
            float sA = hi16 ? sm : sl;
            float rA = __shfl_xor_sync(0xffffffffu, sA, 16);
            float mv = hi16 ? (sl + rA) : (sm + rA);
            mv += __shfl_xor_sync(0xffffffffu, mv, 8);
            mv += __shfl_xor_sync(0xffffffffu, mv, 4);
            mv += __shfl_xor_sync(0xffffffffu, mv, 2);
            mv += __shfl_xor_sync(0xffffffffu, mv, 1);
            fin = ((l & 15) == bb) ? mv : fin;
        }
        const int tb = l & 7;
        float ms = __shfl_sync(0xffffffffu, fin, tb);
        float ls = __shfl_sync(0xffffffffu, fin, tb + 16);
        float mean = fminf(fmaxf(ms + bmj, -1000.0f), 1000.0f);
        float lv   = fminf(fmaxf(ls + blj, -30.0f), 30.0f);
        float s    = fmaf(__expf(0.5f * lv), ep, mean);
        if (l < 8) {
            const int b = Bb + l;
            __stcg(&out[((size_t)b * T + t) * H + j], s);
            if (t == T - 1) out[(size_t)B * T * H + b * H + j] = s;
        }
        release(1);
    };

    // ---------------- main loop: 2 barriers per step ----------------
    for (int t = 0; t < T; t++) {
        const unsigned st = (unsigned)t;

        // prefetch x(t) (no barrier dependency) — overlaps the sample wait
        float4 xv = __ldg((const float4*)(x + ((size_t)(Bb + sb_) * T + t) * D) + sq);

        if (t > 0) waitc(1, c1, st);   // sample(t-1) complete group-wide
        ((float4*)x_s[sb_])[sq] = xv;
        {
            float4 hv;
            if (t == 0) hv = *((const float4*)(h0 + (Bb + sb_) * H) + sq);
            else        hv = __ldcg((const float4*)(out + ((size_t)(Bb + sb_) * T + (t - 1)) * H) + sq);
            ((float4*)hx_s[sb_])[sq] = hv;
        }
        __syncthreads();
        phase1();

        // prefetch eps(t) — overlaps the h_base wait
        float ep = __ldg(eps + ((size_t)(Bb + (l & 7)) * T + t) * H + j);

        waitc(0, c0, st + 1u);         // h_base complete group-wide
        ((float4*)hb_s[sb_])[sq] =
            __ldcg((const float4*)(g_hb + (Bb + sb_) * H) + sq);
        __syncthreads();
        phase2(t, ep);
    }
}

extern "C" void kernel_launch(void* const* d_in, const int* in_sizes, int n_in,
                              void* d_out, int out_size) {
    const float* x   = (const float*)d_in[0];
    const float* h0  = (const float*)d_in[1];
    const float* eps = (const float*)d_in[2];
    const float* Wz  = (const float*)d_in[3];
    const float* bz  = (const float*)d_in[4];
    const float* Wr  = (const float*)d_in[5];
    const float* br  = (const float*)d_in[6];
    const float* Wtx = (const float*)d_in[7];
    const float* btx = (const float*)d_in[8];
    const float* Wth = (const float*)d_in[9];
    const float* bth = (const float*)d_in[10];
    const float* Wd  = (const float*)d_in[11];
    const float* bd  = (const float*)d_in[12];
    float* out = (float*)d_out;

    rgru_kernel<<<NCTA, NTHR>>>(x, h0, eps, Wz, bz, Wr, br,
                                Wtx, btx, Wth, bth, Wd, bd, out);
}